// round 1
// baseline (speedup 1.0000x reference)
#include <cuda_runtime.h>
#include <cuda_fp16.h>
#include <cstdint>

// Problem constants
#define MROWS 8192      // B*C = 32*256
#define VIN   6890
#define VOUT  1723
#define KPAD  6912      // 216 * 32
#define NPAD  1792      // 14 * 128
#define NT    (KPAD/32) // 216 k-tiles

// fp16 scratch (allowed: __device__ globals, no runtime allocation)
__device__ __half g_Xh[(size_t)MROWS * KPAD];  // ~113 MB
__device__ __half g_Mh[(size_t)NPAD  * KPAD];  // ~25 MB

// ---------------- conversion kernels (fp32 -> fp16, zero-padded) -------------
__global__ void convert_x_kernel(const float* __restrict__ x) {
    int k   = blockIdx.x * blockDim.x + threadIdx.x;  // 0..KPAD-1
    int row = blockIdx.y;                             // 0..MROWS-1
    float v = (k < VIN) ? x[(size_t)row * VIN + k] : 0.0f;
    g_Xh[(size_t)row * KPAD + k] = __float2half(v);
}

__global__ void convert_m_kernel(const float* __restrict__ m) {
    int k   = blockIdx.x * blockDim.x + threadIdx.x;
    int row = blockIdx.y;                             // 0..NPAD-1
    float v = (row < VOUT && k < VIN) ? m[(size_t)row * VIN + k] : 0.0f;
    g_Mh[(size_t)row * KPAD + k] = __float2half(v);
}

// ---------------- PTX helpers -----------------------------------------------
__device__ __forceinline__ void cp_async16(void* smem, const void* gmem) {
    uint32_t s = (uint32_t)__cvta_generic_to_shared(smem);
    asm volatile("cp.async.cg.shared.global [%0], [%1], 16;\n" :: "r"(s), "l"(gmem));
}
__device__ __forceinline__ void cp_commit() {
    asm volatile("cp.async.commit_group;\n" ::: "memory");
}
template<int N> __device__ __forceinline__ void cp_wait() {
    asm volatile("cp.async.wait_group %0;\n" :: "n"(N) : "memory");
}
__device__ __forceinline__ void ldsm_x4(uint32_t& r0, uint32_t& r1, uint32_t& r2,
                                        uint32_t& r3, const void* p) {
    uint32_t s = (uint32_t)__cvta_generic_to_shared(p);
    asm volatile("ldmatrix.sync.aligned.m8n8.x4.shared.b16 {%0,%1,%2,%3}, [%4];\n"
                 : "=r"(r0), "=r"(r1), "=r"(r2), "=r"(r3) : "r"(s));
}
__device__ __forceinline__ void mma16816(float* c, const uint32_t* a, const uint32_t* b) {
    asm volatile("mma.sync.aligned.m16n8k16.row.col.f32.f16.f16.f32 "
                 "{%0,%1,%2,%3}, {%4,%5,%6,%7}, {%8,%9}, {%0,%1,%2,%3};\n"
                 : "+f"(c[0]), "+f"(c[1]), "+f"(c[2]), "+f"(c[3])
                 : "r"(a[0]), "r"(a[1]), "r"(a[2]), "r"(a[3]),
                   "r"(b[0]), "r"(b[1]));
}

// ---------------- GEMM: C[8192,1723] = Xh * Mh^T ----------------------------
// Block tile 128x128x32, 8 warps (2x4), warp tile 64x32, mma m16n8k16 f16->f32.
__global__ __launch_bounds__(256, 2) void gemm_kernel(float* __restrict__ out) {
    __shared__ __align__(16) __half As[2][128][40];  // 20 KB (stride 40 -> LDSM conflict-free)
    __shared__ __align__(16) __half Bs[2][128][40];  // 20 KB

    const int tid  = threadIdx.x;
    const int lane = tid & 31;
    const int warp = tid >> 5;
    const int wm   = warp & 1;    // 0..1 -> m offset wm*64
    const int wn   = warp >> 1;   // 0..3 -> n offset wn*32
    const int bm   = blockIdx.y * 128;
    const int bn   = blockIdx.x * 128;

    const __half* Ag = g_Xh + (size_t)bm * KPAD;
    const __half* Bg = g_Mh + (size_t)bn * KPAD;

    // per-thread load map: 512 16B-chunks per tile per operand, 2 per thread
    const int c0   = tid;             // chunk ids: c0, c0+256
    const int r0_  = c0 >> 2;
    const int kc0  = (c0 & 3) * 8;
    const int c1   = tid + 256;
    const int r1_  = c1 >> 2;
    const int kc1  = (c1 & 3) * 8;

    float acc[4][4][4];
    #pragma unroll
    for (int i = 0; i < 4; ++i)
        #pragma unroll
        for (int j = 0; j < 4; ++j)
            #pragma unroll
            for (int e = 0; e < 4; ++e) acc[i][j][e] = 0.0f;

    // prologue: prefetch tile 0 into buf 0
    {
        cp_async16(&As[0][r0_][kc0], Ag + (size_t)r0_ * KPAD + kc0);
        cp_async16(&Bs[0][r0_][kc0], Bg + (size_t)r0_ * KPAD + kc0);
        cp_async16(&As[0][r1_][kc1], Ag + (size_t)r1_ * KPAD + kc1);
        cp_async16(&Bs[0][r1_][kc1], Bg + (size_t)r1_ * KPAD + kc1);
        cp_commit();
    }

    for (int kt = 0; kt < NT; ++kt) {
        const int buf = kt & 1;
        if (kt + 1 < NT) {
            const int nbuf  = buf ^ 1;
            const int kbase = (kt + 1) * 32;
            cp_async16(&As[nbuf][r0_][kc0], Ag + (size_t)r0_ * KPAD + kbase + kc0);
            cp_async16(&Bs[nbuf][r0_][kc0], Bg + (size_t)r0_ * KPAD + kbase + kc0);
            cp_async16(&As[nbuf][r1_][kc1], Ag + (size_t)r1_ * KPAD + kbase + kc1);
            cp_async16(&Bs[nbuf][r1_][kc1], Bg + (size_t)r1_ * KPAD + kbase + kc1);
        }
        cp_commit();
        cp_wait<1>();          // tile kt resident
        __syncthreads();

        #pragma unroll
        for (int ks = 0; ks < 2; ++ks) {
            const int kstep = ks * 16;
            uint32_t a[4][4];
            uint32_t b[4][2];
            #pragma unroll
            for (int i = 0; i < 4; ++i) {
                const int row = wm * 64 + i * 16 + (lane & 15);
                const int col = kstep + (lane >> 4) * 8;
                ldsm_x4(a[i][0], a[i][1], a[i][2], a[i][3], &As[buf][row][col]);
            }
            #pragma unroll
            for (int j = 0; j < 2; ++j) {
                const int nrow = wn * 32 + j * 16 + (lane & 7) + ((lane >> 4) << 3);
                const int col  = kstep + (((lane >> 3) & 1) << 3);
                uint32_t t0, t1, t2, t3;
                ldsm_x4(t0, t1, t2, t3, &Bs[buf][nrow][col]);
                b[2 * j][0] = t0; b[2 * j][1] = t1;
                b[2 * j + 1][0] = t2; b[2 * j + 1][1] = t3;
            }
            #pragma unroll
            for (int i = 0; i < 4; ++i)
                #pragma unroll
                for (int jn = 0; jn < 4; ++jn)
                    mma16816(acc[i][jn], a[i], b[jn]);
        }
        __syncthreads();       // protect buf reuse at kt+2
    }

    // epilogue: fp32 store, guard n < VOUT (rows always < 8192)
    const int g  = lane >> 2;
    const int tc = lane & 3;
    #pragma unroll
    for (int i = 0; i < 4; ++i) {
        #pragma unroll
        for (int jn = 0; jn < 4; ++jn) {
            const int row  = bm + wm * 64 + i * 16 + g;
            const int col  = bn + wn * 32 + jn * 8 + tc * 2;
            if (col < VOUT)     out[(size_t)row * VOUT + col]           = acc[i][jn][0];
            if (col + 1 < VOUT) out[(size_t)row * VOUT + col + 1]       = acc[i][jn][1];
            if (col < VOUT)     out[(size_t)(row + 8) * VOUT + col]     = acc[i][jn][2];
            if (col + 1 < VOUT) out[(size_t)(row + 8) * VOUT + col + 1] = acc[i][jn][3];
        }
    }
}

// ---------------- entry ------------------------------------------------------
extern "C" void kernel_launch(void* const* d_in, const int* in_sizes, int n_in,
                              void* d_out, int out_size) {
    const float* x = (const float*)d_in[0];  // (32,256,6890) fp32
    const float* M = (const float*)d_in[1];  // (1723,6890) fp32
    float* out = (float*)d_out;              // (32,256,1723) fp32

    convert_x_kernel<<<dim3(KPAD / 256, MROWS), 256>>>(x);
    convert_m_kernel<<<dim3(KPAD / 256, NPAD),  256>>>(M);
    gemm_kernel<<<dim3(NPAD / 128, MROWS / 128), 256>>>(out);
}

// round 4
// speedup vs baseline: 1.2333x; 1.2333x over previous
#include <cuda_runtime.h>
#include <cuda_fp16.h>
#include <cstdint>

// ---------------- problem constants -----------------------------------------
#define MROWS 8192      // B*C = 32*256
#define VIN   6890
#define VOUT  1723
#define KPAD  6912      // 108 * 64
#define NPAD  1792      // 7 * 256

// fp16 scratch (device globals; no runtime allocation)
__device__ __align__(16) __half g_Xh[(size_t)MROWS * KPAD];  // ~113 MB
__device__ __align__(16) __half g_Mh[(size_t)NPAD  * KPAD];  // ~25 MB

// ---------------- vectorized fp32 -> fp16 conversion ------------------------
// rows are 8B-aligned (VIN*4 = 27560 ≡ 0 mod 8) -> float2 loads, 16B stores
__global__ void convert_x_v(const float* __restrict__ x) {
    int k8 = blockIdx.x * blockDim.x + threadIdx.x;   // 8-element group
    if (k8 >= KPAD / 8) return;
    int row = blockIdx.y;
    int k = k8 * 8;
    const float* src = x + (size_t)row * VIN + k;
    __align__(16) __half h[8];
    if (k + 8 <= VIN) {
        #pragma unroll
        for (int j = 0; j < 4; ++j) {
            float2 f = *reinterpret_cast<const float2*>(src + 2 * j);
            h[2 * j]     = __float2half(f.x);
            h[2 * j + 1] = __float2half(f.y);
        }
    } else {
        #pragma unroll
        for (int j = 0; j < 8; ++j)
            h[j] = (k + j < VIN) ? __float2half(src[j]) : __float2half(0.0f);
    }
    *reinterpret_cast<uint4*>(&g_Xh[(size_t)row * KPAD + k]) =
        *reinterpret_cast<const uint4*>(h);
}

__global__ void convert_m_v(const float* __restrict__ m) {
    int k8 = blockIdx.x * blockDim.x + threadIdx.x;
    if (k8 >= KPAD / 8) return;
    int row = blockIdx.y;                             // 0..NPAD-1
    int k = k8 * 8;
    __align__(16) __half h[8];
    if (row < VOUT) {
        const float* src = m + (size_t)row * VIN + k;
        if (k + 8 <= VIN) {
            #pragma unroll
            for (int j = 0; j < 4; ++j) {
                float2 f = *reinterpret_cast<const float2*>(src + 2 * j);
                h[2 * j]     = __float2half(f.x);
                h[2 * j + 1] = __float2half(f.y);
            }
        } else {
            #pragma unroll
            for (int j = 0; j < 8; ++j)
                h[j] = (k + j < VIN) ? __float2half(src[j]) : __float2half(0.0f);
        }
    } else {
        #pragma unroll
        for (int j = 0; j < 8; ++j) h[j] = __float2half(0.0f);
    }
    *reinterpret_cast<uint4*>(&g_Mh[(size_t)row * KPAD + k]) =
        *reinterpret_cast<const uint4*>(h);
}

// ---------------- PTX helpers -----------------------------------------------
__device__ __forceinline__ void cp_async16(void* smem, const void* gmem) {
    uint32_t s = (uint32_t)__cvta_generic_to_shared(smem);
    asm volatile("cp.async.cg.shared.global [%0], [%1], 16;\n" :: "r"(s), "l"(gmem));
}
__device__ __forceinline__ void cp_commit() {
    asm volatile("cp.async.commit_group;\n" ::: "memory");
}
template<int N> __device__ __forceinline__ void cp_wait() {
    asm volatile("cp.async.wait_group %0;\n" :: "n"(N) : "memory");
}
__device__ __forceinline__ void ldsm_x4(uint32_t& r0, uint32_t& r1, uint32_t& r2,
                                        uint32_t& r3, const void* p) {
    uint32_t s = (uint32_t)__cvta_generic_to_shared(p);
    asm volatile("ldmatrix.sync.aligned.m8n8.x4.shared.b16 {%0,%1,%2,%3}, [%4];\n"
                 : "=r"(r0), "=r"(r1), "=r"(r2), "=r"(r3) : "r"(s));
}
__device__ __forceinline__ void mma16816(float* c, const uint32_t* a, const uint32_t* b) {
    asm volatile("mma.sync.aligned.m16n8k16.row.col.f32.f16.f16.f32 "
                 "{%0,%1,%2,%3}, {%4,%5,%6,%7}, {%8,%9}, {%0,%1,%2,%3};\n"
                 : "+f"(c[0]), "+f"(c[1]), "+f"(c[2]), "+f"(c[3])
                 : "r"(a[0]), "r"(a[1]), "r"(a[2]), "r"(a[3]),
                   "r"(b[0]), "r"(b[1]));
}

// ---------------- GEMM: C[8192,1723] = Xh * Mh^T ----------------------------
// CTA tile 128(M) x 256(N), KC=64, 3-stage cp.async pipeline.
// 8 warps (2 x 4), warp tile 64x64, mma m16n8k16 f16->f32.
#define BM 128
#define BN 256
#define KC 64
#define STAGES 3
#define NSTG (KPAD / KC)        // 108
#define LDS_K 72                // 64 + 8 pad halves: LDSM conflict-free
#define A_HALVES (BM * LDS_K)   // 9216
#define B_HALVES (BN * LDS_K)   // 18432
#define STG_HALVES (A_HALVES + B_HALVES)       // 27648
#define SMEM_BYTES (STAGES * STG_HALVES * 2)   // 165,888 B

__global__ __launch_bounds__(256, 1) void gemm_kernel(float* __restrict__ out) {
    extern __shared__ __align__(16) __half sm[];

    const int tid  = threadIdx.x;
    const int lane = tid & 31;
    const int warp = tid >> 5;
    const int wm   = warp & 1;    // m offset wm*64
    const int wn   = warp >> 1;   // n offset wn*64
    const int bm   = blockIdx.y * BM;
    const int bn   = blockIdx.x * BN;

    const __half* Ag = g_Xh + (size_t)bm * KPAD;
    const __half* Bg = g_Mh + (size_t)bn * KPAD;

    // per-thread cp.async map: 16B chunks; row = c>>3, k16 = c&7 (8 chunks/row)
    auto loadStage = [&](int s) {
        __half* aS = sm + (s % STAGES) * STG_HALVES;
        __half* bS = aS + A_HALVES;
        const int kb = s * KC;
        #pragma unroll
        for (int i = 0; i < 4; ++i) {          // A: 1024 chunks / 256 thr
            const int c = tid + i * 256;
            const int r = c >> 3, k16 = c & 7;
            cp_async16(aS + r * LDS_K + k16 * 8,
                       Ag + (size_t)r * KPAD + kb + k16 * 8);
        }
        #pragma unroll
        for (int i = 0; i < 8; ++i) {          // B: 2048 chunks / 256 thr
            const int c = tid + i * 256;
            const int r = c >> 3, k16 = c & 7;
            cp_async16(bS + r * LDS_K + k16 * 8,
                       Bg + (size_t)r * KPAD + kb + k16 * 8);
        }
    };

    float acc[4][8][4];
    #pragma unroll
    for (int i = 0; i < 4; ++i)
        #pragma unroll
        for (int j = 0; j < 8; ++j)
            #pragma unroll
            for (int e = 0; e < 4; ++e) acc[i][j][e] = 0.0f;

    // prologue
    loadStage(0); cp_commit();
    loadStage(1); cp_commit();
    cp_wait<1>();
    __syncthreads();               // stage 0 resident

    for (int kt = 0; kt < NSTG; ++kt) {
        // issue loads for kt+2 (that slot's previous stage was consumed
        // before the barrier that ended iteration kt-1)
        if (kt + 2 < NSTG) loadStage(kt + 2);
        cp_commit();

        const __half* aS = sm + (kt % STAGES) * STG_HALVES;
        const __half* bS = aS + A_HALVES;

        #pragma unroll
        for (int ks = 0; ks < 4; ++ks) {
            const int kstep = ks * 16;
            uint32_t a[4][4];
            uint32_t b[8][2];
            #pragma unroll
            for (int i = 0; i < 4; ++i) {
                const int row = wm * 64 + i * 16 + (lane & 15);
                const int col = kstep + (lane >> 4) * 8;
                ldsm_x4(a[i][0], a[i][1], a[i][2], a[i][3], aS + row * LDS_K + col);
            }
            #pragma unroll
            for (int j = 0; j < 4; ++j) {
                const int nrow = wn * 64 + j * 16 + (lane & 7) + ((lane >> 4) << 3);
                const int col  = kstep + (((lane >> 3) & 1) << 3);
                uint32_t t0, t1, t2, t3;
                ldsm_x4(t0, t1, t2, t3, bS + nrow * LDS_K + col);
                b[2 * j][0] = t0;     b[2 * j][1] = t1;
                b[2 * j + 1][0] = t2; b[2 * j + 1][1] = t3;
            }
            #pragma unroll
            for (int i = 0; i < 4; ++i)
                #pragma unroll
                for (int jn = 0; jn < 8; ++jn)
                    mma16816(acc[i][jn], a[i], b[jn]);
        }

        cp_wait<1>();
        __syncthreads();           // stage kt+1 resident; all warps done with kt
    }

    // epilogue: scalar fp32 stores (VOUT=1723 is odd -> float2 would misalign
    // on odd rows). Rows always < 8192; guard n < VOUT.
    const int g  = lane >> 2;
    const int tc = lane & 3;
    #pragma unroll
    for (int i = 0; i < 4; ++i) {
        #pragma unroll
        for (int jn = 0; jn < 8; ++jn) {
            const int row = bm + wm * 64 + i * 16 + g;
            const int col = bn + wn * 64 + jn * 8 + tc * 2;
            if (col < VOUT)     out[(size_t)row * VOUT + col]           = acc[i][jn][0];
            if (col + 1 < VOUT) out[(size_t)row * VOUT + col + 1]       = acc[i][jn][1];
            if (col < VOUT)     out[(size_t)(row + 8) * VOUT + col]     = acc[i][jn][2];
            if (col + 1 < VOUT) out[(size_t)(row + 8) * VOUT + col + 1] = acc[i][jn][3];
        }
    }
}

// ---------------- entry ------------------------------------------------------
extern "C" void kernel_launch(void* const* d_in, const int* in_sizes, int n_in,
                              void* d_out, int out_size) {
    const float* x = (const float*)d_in[0];  // (32,256,6890) fp32
    const float* M = (const float*)d_in[1];  // (1723,6890) fp32
    float* out = (float*)d_out;              // (32,256,1723) fp32

    cudaFuncSetAttribute(gemm_kernel, cudaFuncAttributeMaxDynamicSharedMemorySize,
                         SMEM_BYTES);

    convert_x_v<<<dim3((KPAD / 8 + 127) / 128, MROWS), 128>>>(x);
    convert_m_v<<<dim3((KPAD / 8 + 127) / 128, NPAD),  128>>>(M);
    gemm_kernel<<<dim3(NPAD / BN, MROWS / BM), 256, SMEM_BYTES>>>(out);
}

// round 5
// speedup vs baseline: 1.3280x; 1.0767x over previous
#include <cuda_runtime.h>
#include <cuda_fp16.h>
#include <cstdint>

// ---------------- problem constants -----------------------------------------
#define MROWS 8192      // B*C = 32*256
#define VIN   6890
#define VOUT  1723
#define KPAD  6912      // 108 * 64
#define NPAD  1792      // 14 * 128

// fp16 scratch (device globals; no runtime allocation)
__device__ __align__(16) __half g_Xh[(size_t)MROWS * KPAD];  // ~113 MB
__device__ __align__(16) __half g_Mh[(size_t)NPAD  * KPAD];  // ~25 MB

// ---------------- vectorized fp32 -> fp16 conversion ------------------------
__global__ void convert_x_v(const float* __restrict__ x) {
    int k8 = blockIdx.x * blockDim.x + threadIdx.x;   // 8-element group
    if (k8 >= KPAD / 8) return;
    int row = blockIdx.y;
    int k = k8 * 8;
    const float* src = x + (size_t)row * VIN + k;
    __align__(16) __half h[8];
    if (k + 8 <= VIN) {
        #pragma unroll
        for (int j = 0; j < 4; ++j) {
            float2 f = *reinterpret_cast<const float2*>(src + 2 * j);
            h[2 * j]     = __float2half(f.x);
            h[2 * j + 1] = __float2half(f.y);
        }
    } else {
        #pragma unroll
        for (int j = 0; j < 8; ++j)
            h[j] = (k + j < VIN) ? __float2half(src[j]) : __float2half(0.0f);
    }
    *reinterpret_cast<uint4*>(&g_Xh[(size_t)row * KPAD + k]) =
        *reinterpret_cast<const uint4*>(h);
}

__global__ void convert_m_v(const float* __restrict__ m) {
    int k8 = blockIdx.x * blockDim.x + threadIdx.x;
    if (k8 >= KPAD / 8) return;
    int row = blockIdx.y;                             // 0..NPAD-1
    int k = k8 * 8;
    __align__(16) __half h[8];
    if (row < VOUT) {
        const float* src = m + (size_t)row * VIN + k;
        if (k + 8 <= VIN) {
            #pragma unroll
            for (int j = 0; j < 4; ++j) {
                float2 f = *reinterpret_cast<const float2*>(src + 2 * j);
                h[2 * j]     = __float2half(f.x);
                h[2 * j + 1] = __float2half(f.y);
            }
        } else {
            #pragma unroll
            for (int j = 0; j < 8; ++j)
                h[j] = (k + j < VIN) ? __float2half(src[j]) : __float2half(0.0f);
        }
    } else {
        #pragma unroll
        for (int j = 0; j < 8; ++j) h[j] = __float2half(0.0f);
    }
    *reinterpret_cast<uint4*>(&g_Mh[(size_t)row * KPAD + k]) =
        *reinterpret_cast<const uint4*>(h);
}

// ---------------- PTX helpers -----------------------------------------------
__device__ __forceinline__ void cp_async16(void* smem, const void* gmem) {
    uint32_t s = (uint32_t)__cvta_generic_to_shared(smem);
    asm volatile("cp.async.cg.shared.global [%0], [%1], 16;\n" :: "r"(s), "l"(gmem));
}
__device__ __forceinline__ void cp_commit() {
    asm volatile("cp.async.commit_group;\n" ::: "memory");
}
template<int N> __device__ __forceinline__ void cp_wait() {
    asm volatile("cp.async.wait_group %0;\n" :: "n"(N) : "memory");
}
__device__ __forceinline__ void ldsm_x4(uint32_t& r0, uint32_t& r1, uint32_t& r2,
                                        uint32_t& r3, const void* p) {
    uint32_t s = (uint32_t)__cvta_generic_to_shared(p);
    asm volatile("ldmatrix.sync.aligned.m8n8.x4.shared.b16 {%0,%1,%2,%3}, [%4];\n"
                 : "=r"(r0), "=r"(r1), "=r"(r2), "=r"(r3) : "r"(s));
}
__device__ __forceinline__ void mma16816(float* c, const uint32_t* a, const uint32_t* b) {
    asm volatile("mma.sync.aligned.m16n8k16.row.col.f32.f16.f16.f32 "
                 "{%0,%1,%2,%3}, {%4,%5,%6,%7}, {%8,%9}, {%0,%1,%2,%3};\n"
                 : "+f"(c[0]), "+f"(c[1]), "+f"(c[2]), "+f"(c[3])
                 : "r"(a[0]), "r"(a[1]), "r"(a[2]), "r"(a[3]),
                   "r"(b[0]), "r"(b[1]));
}

// ---------------- GEMM: C[8192,1723] = Xh * Mh^T ----------------------------
// CTA tile 128x128, KC=64, 3-stage cp.async pipeline, 2 CTAs/SM.
// 8 warps (2 x 4), warp tile 64x32, mma m16n8k16 f16->f32.
#define BM 128
#define BN 128
#define KC 64
#define STAGES 3
#define NSTG (KPAD / KC)        // 108
#define LDS_K 72                // 64 + 8 pad halves: LDSM conflict-free
#define A_HALVES (BM * LDS_K)   // 9216
#define B_HALVES (BN * LDS_K)   // 9216
#define STG_HALVES (A_HALVES + B_HALVES)       // 18432
#define SMEM_BYTES (STAGES * STG_HALVES * 2)   // 110,592 B per CTA

__global__ __launch_bounds__(256, 2) void gemm_kernel(float* __restrict__ out) {
    extern __shared__ __align__(16) __half sm[];

    const int tid  = threadIdx.x;
    const int lane = tid & 31;
    const int warp = tid >> 5;
    const int wm   = warp & 1;    // m offset wm*64
    const int wn   = warp >> 1;   // n offset wn*32
    const int bm   = blockIdx.y * BM;
    const int bn   = blockIdx.x * BN;

    const __half* Ag = g_Xh + (size_t)bm * KPAD;
    const __half* Bg = g_Mh + (size_t)bn * KPAD;

    // per-thread cp.async map: 16B chunks; row = c>>3, k16 = c&7 (8 chunks/row)
    auto loadStage = [&](int s) {
        __half* aS = sm + (s % STAGES) * STG_HALVES;
        __half* bS = aS + A_HALVES;
        const int kb = s * KC;
        #pragma unroll
        for (int i = 0; i < 4; ++i) {          // A: 1024 chunks / 256 thr
            const int c = tid + i * 256;
            const int r = c >> 3, k16 = c & 7;
            cp_async16(aS + r * LDS_K + k16 * 8,
                       Ag + (size_t)r * KPAD + kb + k16 * 8);
        }
        #pragma unroll
        for (int i = 0; i < 4; ++i) {          // B: 1024 chunks / 256 thr
            const int c = tid + i * 256;
            const int r = c >> 3, k16 = c & 7;
            cp_async16(bS + r * LDS_K + k16 * 8,
                       Bg + (size_t)r * KPAD + kb + k16 * 8);
        }
    };

    float acc[4][4][4];
    #pragma unroll
    for (int i = 0; i < 4; ++i)
        #pragma unroll
        for (int j = 0; j < 4; ++j)
            #pragma unroll
            for (int e = 0; e < 4; ++e) acc[i][j][e] = 0.0f;

    // prologue
    loadStage(0); cp_commit();
    loadStage(1); cp_commit();
    cp_wait<1>();
    __syncthreads();               // stage 0 resident

    for (int kt = 0; kt < NSTG; ++kt) {
        // issue loads for kt+2 (slot's previous stage consumed before the
        // barrier that ended iteration kt-1)
        if (kt + 2 < NSTG) loadStage(kt + 2);
        cp_commit();

        const __half* aS = sm + (kt % STAGES) * STG_HALVES;
        const __half* bS = aS + A_HALVES;

        #pragma unroll
        for (int ks = 0; ks < 4; ++ks) {
            const int kstep = ks * 16;
            uint32_t a[4][4];
            uint32_t b[4][2];
            #pragma unroll
            for (int i = 0; i < 4; ++i) {
                const int row = wm * 64 + i * 16 + (lane & 15);
                const int col = kstep + (lane >> 4) * 8;
                ldsm_x4(a[i][0], a[i][1], a[i][2], a[i][3], aS + row * LDS_K + col);
            }
            #pragma unroll
            for (int j = 0; j < 2; ++j) {
                const int nrow = wn * 32 + j * 16 + (lane & 7) + ((lane >> 4) << 3);
                const int col  = kstep + (((lane >> 3) & 1) << 3);
                uint32_t t0, t1, t2, t3;
                ldsm_x4(t0, t1, t2, t3, bS + nrow * LDS_K + col);
                b[2 * j][0] = t0;     b[2 * j][1] = t1;
                b[2 * j + 1][0] = t2; b[2 * j + 1][1] = t3;
            }
            #pragma unroll
            for (int i = 0; i < 4; ++i)
                #pragma unroll
                for (int jn = 0; jn < 4; ++jn)
                    mma16816(acc[i][jn], a[i], b[jn]);
        }

        cp_wait<1>();
        __syncthreads();           // stage kt+1 resident; all warps done with kt
    }

    // epilogue: scalar fp32 stores (VOUT=1723 odd -> no vector stores).
    const int g  = lane >> 2;
    const int tc = lane & 3;
    #pragma unroll
    for (int i = 0; i < 4; ++i) {
        #pragma unroll
        for (int jn = 0; jn < 4; ++jn) {
            const int row = bm + wm * 64 + i * 16 + g;
            const int col = bn + wn * 32 + jn * 8 + tc * 2;
            if (col < VOUT)     out[(size_t)row * VOUT + col]           = acc[i][jn][0];
            if (col + 1 < VOUT) out[(size_t)row * VOUT + col + 1]       = acc[i][jn][1];
            if (col < VOUT)     out[(size_t)(row + 8) * VOUT + col]     = acc[i][jn][2];
            if (col + 1 < VOUT) out[(size_t)(row + 8) * VOUT + col + 1] = acc[i][jn][3];
        }
    }
}

// ---------------- entry ------------------------------------------------------
extern "C" void kernel_launch(void* const* d_in, const int* in_sizes, int n_in,
                              void* d_out, int out_size) {
    const float* x = (const float*)d_in[0];  // (32,256,6890) fp32
    const float* M = (const float*)d_in[1];  // (1723,6890) fp32
    float* out = (float*)d_out;              // (32,256,1723) fp32

    cudaFuncSetAttribute(gemm_kernel, cudaFuncAttributeMaxDynamicSharedMemorySize,
                         SMEM_BYTES);

    convert_x_v<<<dim3((KPAD / 8 + 127) / 128, MROWS), 128>>>(x);
    convert_m_v<<<dim3((KPAD / 8 + 127) / 128, NPAD),  128>>>(M);
    gemm_kernel<<<dim3(NPAD / BN, MROWS / BM), 256, SMEM_BYTES>>>(out);
}

// round 6
// speedup vs baseline: 1.3305x; 1.0020x over previous
#include <cuda_runtime.h>
#include <cuda_fp16.h>
#include <cstdint>

// ---------------- problem constants -----------------------------------------
#define MROWS 8192      // B*C = 32*256
#define VIN   6890
#define VOUT  1723
#define KPAD  6912      // 108 * 64
#define NPAD  1792      // 14 * 128

// fp16 scratch (device globals; no runtime allocation)
__device__ __align__(16) __half g_Xh[(size_t)MROWS * KPAD];  // ~113 MB
__device__ __align__(16) __half g_Mh[(size_t)NPAD  * KPAD];  // ~25 MB

// ---------------- vectorized fp32 -> fp16 conversion ------------------------
__global__ void convert_x_v(const float* __restrict__ x) {
    int k8 = blockIdx.x * blockDim.x + threadIdx.x;   // 8-element group
    if (k8 >= KPAD / 8) return;
    int row = blockIdx.y;
    int k = k8 * 8;
    const float* src = x + (size_t)row * VIN + k;
    __align__(16) __half h[8];
    if (k + 8 <= VIN) {
        #pragma unroll
        for (int j = 0; j < 4; ++j) {
            float2 f = *reinterpret_cast<const float2*>(src + 2 * j);
            h[2 * j]     = __float2half(f.x);
            h[2 * j + 1] = __float2half(f.y);
        }
    } else {
        #pragma unroll
        for (int j = 0; j < 8; ++j)
            h[j] = (k + j < VIN) ? __float2half(src[j]) : __float2half(0.0f);
    }
    *reinterpret_cast<uint4*>(&g_Xh[(size_t)row * KPAD + k]) =
        *reinterpret_cast<const uint4*>(h);
}

__global__ void convert_m_v(const float* __restrict__ m) {
    int k8 = blockIdx.x * blockDim.x + threadIdx.x;
    if (k8 >= KPAD / 8) return;
    int row = blockIdx.y;                             // 0..NPAD-1
    int k = k8 * 8;
    __align__(16) __half h[8];
    if (row < VOUT) {
        const float* src = m + (size_t)row * VIN + k;
        if (k + 8 <= VIN) {
            #pragma unroll
            for (int j = 0; j < 4; ++j) {
                float2 f = *reinterpret_cast<const float2*>(src + 2 * j);
                h[2 * j]     = __float2half(f.x);
                h[2 * j + 1] = __float2half(f.y);
            }
        } else {
            #pragma unroll
            for (int j = 0; j < 8; ++j)
                h[j] = (k + j < VIN) ? __float2half(src[j]) : __float2half(0.0f);
        }
    } else {
        #pragma unroll
        for (int j = 0; j < 8; ++j) h[j] = __float2half(0.0f);
    }
    *reinterpret_cast<uint4*>(&g_Mh[(size_t)row * KPAD + k]) =
        *reinterpret_cast<const uint4*>(h);
}

// ---------------- PTX helpers -----------------------------------------------
__device__ __forceinline__ void cp_async16(void* smem, const void* gmem) {
    uint32_t s = (uint32_t)__cvta_generic_to_shared(smem);
    asm volatile("cp.async.cg.shared.global [%0], [%1], 16;\n" :: "r"(s), "l"(gmem));
}
__device__ __forceinline__ void cp_commit() {
    asm volatile("cp.async.commit_group;\n" ::: "memory");
}
template<int N> __device__ __forceinline__ void cp_wait() {
    asm volatile("cp.async.wait_group %0;\n" :: "n"(N) : "memory");
}
__device__ __forceinline__ void ldsm_x4(uint32_t& r0, uint32_t& r1, uint32_t& r2,
                                        uint32_t& r3, const void* p) {
    uint32_t s = (uint32_t)__cvta_generic_to_shared(p);
    asm volatile("ldmatrix.sync.aligned.m8n8.x4.shared.b16 {%0,%1,%2,%3}, [%4];\n"
                 : "=r"(r0), "=r"(r1), "=r"(r2), "=r"(r3) : "r"(s));
}
__device__ __forceinline__ void mma16816(float* c, const uint32_t* a, const uint32_t* b) {
    asm volatile("mma.sync.aligned.m16n8k16.row.col.f32.f16.f16.f32 "
                 "{%0,%1,%2,%3}, {%4,%5,%6,%7}, {%8,%9}, {%0,%1,%2,%3};\n"
                 : "+f"(c[0]), "+f"(c[1]), "+f"(c[2]), "+f"(c[3])
                 : "r"(a[0]), "r"(a[1]), "r"(a[2]), "r"(a[3]),
                   "r"(b[0]), "r"(b[1]));
}

// ---------------- GEMM: C[8192,1723] = Xh * Mh^T ----------------------------
// CTA tile 128x128, KC=64, 3-stage cp.async pipeline, 2 CTAs/SM.
// 8 warps (2 x 4), warp tile 64x32, mma m16n8k16 f16->f32.
#define BM 128
#define BN 128
#define KC 64
#define STAGES 3
#define NSTG (KPAD / KC)        // 108
#define LDS_K 72                // 64 + 8 pad halves: LDSM conflict-free
#define A_HALVES (BM * LDS_K)   // 9216
#define B_HALVES (BN * LDS_K)   // 9216
#define STG_HALVES (A_HALVES + B_HALVES)       // 18432
#define SMEM_BYTES (STAGES * STG_HALVES * 2)   // 110,592 B per CTA

__global__ __launch_bounds__(256, 2) void gemm_kernel(float* __restrict__ out) {
    extern __shared__ __align__(16) __half sm[];

    const int tid  = threadIdx.x;
    const int lane = tid & 31;
    const int warp = tid >> 5;
    const int wm   = warp & 1;    // m offset wm*64
    const int wn   = warp >> 1;   // n offset wn*32
    const int bm   = blockIdx.y * BM;
    const int bn   = blockIdx.x * BN;

    const __half* Ag = g_Xh + (size_t)bm * KPAD;
    const __half* Bg = g_Mh + (size_t)bn * KPAD;

    // per-thread cp.async map: 16B chunks; row = c>>3, k16 = c&7 (8 chunks/row)
    auto loadStage = [&](int s) {
        __half* aS = sm + (s % STAGES) * STG_HALVES;
        __half* bS = aS + A_HALVES;
        const int kb = s * KC;
        #pragma unroll
        for (int i = 0; i < 4; ++i) {          // A: 1024 chunks / 256 thr
            const int c = tid + i * 256;
            const int r = c >> 3, k16 = c & 7;
            cp_async16(aS + r * LDS_K + k16 * 8,
                       Ag + (size_t)r * KPAD + kb + k16 * 8);
        }
        #pragma unroll
        for (int i = 0; i < 4; ++i) {          // B: 1024 chunks / 256 thr
            const int c = tid + i * 256;
            const int r = c >> 3, k16 = c & 7;
            cp_async16(bS + r * LDS_K + k16 * 8,
                       Bg + (size_t)r * KPAD + kb + k16 * 8);
        }
    };

    float acc[4][4][4];
    #pragma unroll
    for (int i = 0; i < 4; ++i)
        #pragma unroll
        for (int j = 0; j < 4; ++j)
            #pragma unroll
            for (int e = 0; e < 4; ++e) acc[i][j][e] = 0.0f;

    // prologue
    loadStage(0); cp_commit();
    loadStage(1); cp_commit();
    cp_wait<1>();
    __syncthreads();               // stage 0 resident

    for (int kt = 0; kt < NSTG; ++kt) {
        // issue loads for kt+2 (slot's previous stage consumed before the
        // barrier that ended iteration kt-1)
        if (kt + 2 < NSTG) loadStage(kt + 2);
        cp_commit();

        const __half* aS = sm + (kt % STAGES) * STG_HALVES;
        const __half* bS = aS + A_HALVES;

        #pragma unroll
        for (int ks = 0; ks < 4; ++ks) {
            const int kstep = ks * 16;
            uint32_t a[4][4];
            uint32_t b[4][2];
            #pragma unroll
            for (int i = 0; i < 4; ++i) {
                const int row = wm * 64 + i * 16 + (lane & 15);
                const int col = kstep + (lane >> 4) * 8;
                ldsm_x4(a[i][0], a[i][1], a[i][2], a[i][3], aS + row * LDS_K + col);
            }
            #pragma unroll
            for (int j = 0; j < 2; ++j) {
                const int nrow = wn * 32 + j * 16 + (lane & 7) + ((lane >> 4) << 3);
                const int col  = kstep + (((lane >> 3) & 1) << 3);
                uint32_t t0, t1, t2, t3;
                ldsm_x4(t0, t1, t2, t3, bS + nrow * LDS_K + col);
                b[2 * j][0] = t0;     b[2 * j][1] = t1;
                b[2 * j + 1][0] = t2; b[2 * j + 1][1] = t3;
            }
            #pragma unroll
            for (int i = 0; i < 4; ++i)
                #pragma unroll
                for (int jn = 0; jn < 4; ++jn)
                    mma16816(acc[i][jn], a[i], b[jn]);
        }

        cp_wait<1>();
        __syncthreads();           // stage kt+1 resident; all warps done with kt
    }

    // epilogue: scalar fp32 stores (VOUT=1723 odd -> no vector stores).
    const int g  = lane >> 2;
    const int tc = lane & 3;
    #pragma unroll
    for (int i = 0; i < 4; ++i) {
        #pragma unroll
        for (int jn = 0; jn < 4; ++jn) {
            const int row = bm + wm * 64 + i * 16 + g;
            const int col = bn + wn * 32 + jn * 8 + tc * 2;
            if (col < VOUT)     out[(size_t)row * VOUT + col]           = acc[i][jn][0];
            if (col + 1 < VOUT) out[(size_t)row * VOUT + col + 1]       = acc[i][jn][1];
            if (col < VOUT)     out[(size_t)(row + 8) * VOUT + col]     = acc[i][jn][2];
            if (col + 1 < VOUT) out[(size_t)(row + 8) * VOUT + col + 1] = acc[i][jn][3];
        }
    }
}

// ---------------- entry ------------------------------------------------------
extern "C" void kernel_launch(void* const* d_in, const int* in_sizes, int n_in,
                              void* d_out, int out_size) {
    const float* x = (const float*)d_in[0];  // (32,256,6890) fp32
    const float* M = (const float*)d_in[1];  // (1723,6890) fp32
    float* out = (float*)d_out;              // (32,256,1723) fp32

    cudaFuncSetAttribute(gemm_kernel, cudaFuncAttributeMaxDynamicSharedMemorySize,
                         SMEM_BYTES);

    convert_x_v<<<dim3((KPAD / 8 + 127) / 128, MROWS), 128>>>(x);
    convert_m_v<<<dim3((KPAD / 8 + 127) / 128, NPAD),  128>>>(M);
    gemm_kernel<<<dim3(NPAD / BN, MROWS / BM), 256, SMEM_BYTES>>>(out);
}